// round 13
// baseline (speedup 1.0000x reference)
#include <cuda_runtime.h>
#include <math.h>

#define NN 231
#define BT 8
#define THREADS 512
#define NWARP 16
#define MAXM 4096     // padded-to-4 edges <= 231*4 + 2079 ~ 3003

#define S1S 68    // t1 row stride: 64 data + 4 (bank rotate, 16B aligned)
#define S2S 36    // t2 row stride: 32 + 4
#define T3S 20    // t3 row stride: 16 + 4
#define XFSD 944  // duplicated FC input stride per graph (928 used + 16 pad)
#define H1S 124   // FC1 out stride
#define H2S 92    // FC2 out stride

typedef unsigned long long ull;

// ---------------- persistent CSR built by prep kernel ----------------
__device__ int    g_row_ptr[NN + 1];
__device__ float2 g_csr_e[MAXM];    // (w, src-as-float-bits)

// =====================================================================
// Prep: deterministic CSR (stable counting sort by dst); each row padded
// to a multiple of 4 with (w=0, src=0) dummies.
// =====================================================================
__global__ void prep_kernel(const void* __restrict__ ei, int E) {
    __shared__ short s_src[2304];
    __shared__ short s_dst[2304];
    __shared__ int   deg[NN];
    __shared__ int   pdeg[NN];
    __shared__ int   rp[NN + 1];
    __shared__ float inv[NN];
    __shared__ int   cnt[32][NN];
    __shared__ int   is64;

    const int tid = threadIdx.x;
    const int M = E + NN;

    if (tid == 0) {
        const long long* p = (const long long*)ei;
        int ok = 1;
        for (int i = 0; i < 8; i++) {
            long long v = p[i];
            if (v < 0 || v >= NN) ok = 0;
        }
        is64 = ok;
    }
    for (int n = tid; n < NN; n += blockDim.x) deg[n] = 0;
    __syncthreads();

    for (int e = tid; e < M; e += blockDim.x) {
        int s, d;
        if (e < E) {
            if (is64) {
                s = (int)((const long long*)ei)[e];
                d = (int)((const long long*)ei)[E + e];
            } else {
                s = ((const int*)ei)[e];
                d = ((const int*)ei)[E + e];
            }
        } else {
            s = d = e - E;   // self loops appended after real edges
        }
        s_src[e] = (short)s;
        s_dst[e] = (short)d;
        atomicAdd(&deg[d], 1);
    }
    __syncthreads();

    for (int n = tid; n < NN; n += blockDim.x) {
        inv[n]  = rsqrtf((float)max(deg[n], 1));
        pdeg[n] = (deg[n] + 3) & ~3;
    }
    __syncthreads();
    if (tid == 0) {
        int acc = 0;
        for (int n = 0; n < NN; n++) { rp[n] = acc; acc += pdeg[n]; }
        rp[NN] = acc;
    }
    for (int i = tid; i < 32 * NN; i += blockDim.x)
        ((int*)cnt)[i] = 0;
    __syncthreads();

    const int chunk = (M + 31) / 32;
    if (tid < 32) {
        int e0 = tid * chunk, e1 = min(e0 + chunk, M);
        for (int e = e0; e < e1; e++) cnt[tid][s_dst[e]]++;
    }
    __syncthreads();

    for (int n = tid; n < NN; n += blockDim.x) {
        int run = rp[n];
        for (int t = 0; t < 32; t++) {
            int c = cnt[t][n];
            cnt[t][n] = run;
            run += c;
        }
    }
    __syncthreads();

    if (tid < 32) {
        int e0 = tid * chunk, e1 = min(e0 + chunk, M);
        for (int e = e0; e < e1; e++) {
            int d = s_dst[e], s = s_src[e];
            int pos = cnt[tid][d]++;
            g_csr_e[pos] = make_float2(inv[s] * inv[d], __int_as_float(s));
        }
    }
    __syncthreads();

    // pad rows with dummy edges (w=0, src=0)
    for (int n = tid; n < NN; n += blockDim.x) {
        for (int p = deg[n]; p < pdeg[n]; p++)
            g_csr_e[rp[n] + p] = make_float2(0.0f, __int_as_float(0));
    }
    for (int n = tid; n <= NN; n += blockDim.x) g_row_ptr[n] = rp[n];
}

// =====================================================================
__device__ __forceinline__ float htanh(float x) {
    float y;
    asm("tanh.approx.f32 %0, %1;" : "=f"(y) : "f"(x));
    return y;
}
__device__ __forceinline__ float elu1(float v) {
    return v > 0.0f ? v : (__expf(v) - 1.0f);
}
__device__ __forceinline__ ull ffma2(ull a, ull b, ull c) {
    ull d;
    asm("fma.rn.f32x2 %0, %1, %2, %3;" : "=l"(d) : "l"(a), "l"(b), "l"(c));
    return d;
}
__device__ __forceinline__ ull bcast2(float x) {
    ull d;
    asm("mov.b64 %0, {%1, %1};" : "=l"(d) : "r"(__float_as_uint(x)));
    return d;
}
__device__ __forceinline__ float2 unpack2(ull d) {
    unsigned int lo, hi;
    asm("mov.b64 {%0, %1}, %2;" : "=r"(lo), "=r"(hi) : "l"(d));
    return make_float2(__int_as_float(lo), __int_as_float(hi));
}

// small-weight shared offsets (floats)
#define O_W1  0      // 12x8 (unused by T1 now, kept for layout)
#define O_B1  96     // 8
#define O_W2  104    // 8x4
#define O_B2  136    // 4
#define O_W3  140    // 4x2
#define O_B3  148    // 2
#define O_BF1 152    // 120
#define O_BF2 272    // 84
#define O_BF3 356    // 10
#define SMALLSZ 384

#define SM_FLOATS (NN*S1S + NN*S2S + SMALLSZ)
#define SM_BYTES  (SM_FLOATS*4 + (NN+1)*4)

__global__ void __launch_bounds__(THREADS, 2)
gcn_fused_kernel(const float* __restrict__ x,
                 const float* __restrict__ W1, const float* __restrict__ b1,
                 const float* __restrict__ W2, const float* __restrict__ b2,
                 const float* __restrict__ W3, const float* __restrict__ b3,
                 const float* __restrict__ Wf1, const float* __restrict__ bf1,
                 const float* __restrict__ Wf2, const float* __restrict__ bf2,
                 const float* __restrict__ Wf3, const float* __restrict__ bf3,
                 float* __restrict__ out, int B) {
    extern __shared__ float sm[];
    float*  S1      = sm;                  // t1 [n][b8][f8], stride 68
    float*  S2      = S1 + NN * S1S;       // t2 [n][b8][f4], stride 36 / xfc-dup
    float*  s_small = S2 + NN * S2S;
    int*    s_rp    = (int*)(s_small + SMALLSZ);

    const int tid  = threadIdx.x;
    const int wid  = tid >> 5;
    const int lane = tid & 31;
    const int b0   = blockIdx.x * BT;

    // ---- stage rp + small weights (NO barrier: T1 below reads only
    //      global memory; barrier after T1 publishes everything) ----
    for (int i = tid; i <= NN; i += THREADS) s_rp[i] = g_row_ptr[i];
    for (int i = tid; i < 8;   i += THREADS) s_small[O_B1 + i] = b1[i];
    for (int i = tid; i < 32;  i += THREADS) s_small[O_W2 + i] = W2[i];
    for (int i = tid; i < 4;   i += THREADS) s_small[O_B2 + i] = b2[i];
    for (int i = tid; i < 8;   i += THREADS) s_small[O_W3 + i] = W3[i];
    for (int i = tid; i < 2;   i += THREADS) s_small[O_B3 + i] = b3[i];
    for (int i = tid; i < 120; i += THREADS) s_small[O_BF1 + i] = bf1[i];
    for (int i = tid; i < 84;  i += THREADS) s_small[O_BF2 + i] = bf2[i];
    for (int i = tid; i < 10;  i += THREADS) s_small[O_BF3 + i] = bf3[i];

    // ========== T1: t1 = x @ W1 -> S1[n][b][f]  (W1 via __ldg) =======
    for (int idx = tid; idx < NN * BT; idx += THREADS) {
        const int b = idx / NN, n = idx - b * NN;
        const int g = b0 + b;
        float xa[12];
        if (g < B) {
            const float4* xp = (const float4*)(x + ((size_t)g * NN + n) * 12);
            float4 v0 = __ldg(xp), v1 = __ldg(xp + 1), v2 = __ldg(xp + 2);
            xa[0] = v0.x; xa[1] = v0.y; xa[2]  = v0.z; xa[3]  = v0.w;
            xa[4] = v1.x; xa[5] = v1.y; xa[6]  = v1.z; xa[7]  = v1.w;
            xa[8] = v2.x; xa[9] = v2.y; xa[10] = v2.z; xa[11] = v2.w;
        } else {
            #pragma unroll
            for (int c = 0; c < 12; c++) xa[c] = 0.0f;
        }
        ull p0 = 0, p1 = 0, p2 = 0, p3 = 0;
        #pragma unroll
        for (int c = 0; c < 12; c++) {
            const ull xb = bcast2(xa[c]);
            const ull* wrow = (const ull*)(W1 + c * 8);
            p0 = ffma2(xb, __ldg(wrow + 0), p0);
            p1 = ffma2(xb, __ldg(wrow + 1), p1);
            p2 = ffma2(xb, __ldg(wrow + 2), p2);
            p3 = ffma2(xb, __ldg(wrow + 3), p3);
        }
        float* dst = S1 + n * S1S + b * 8;
        *(ulonglong2*)dst       = make_ulonglong2(p0, p1);
        *(ulonglong2*)(dst + 4) = make_ulonglong2(p2, p3);
    }
    __syncthreads();

    // ========== A1: h1 = tanh(agg(t1)+b1); t2 = h1@W2 -> S2 ==========
    // half-warp per edge, 2 edges/lane/iter, clamped prefetch;
    // lh owns float4: b = lh>>1, fq = (lh&1)*4
    {
        const int h  = lane >> 4;
        const int lh = lane & 15;
        const int fq = (lh & 1) * 4;
        ull wp01[4], wp23[4];
        #pragma unroll
        for (int i = 0; i < 4; i++) {
            wp01[i] = *(const ull*)(s_small + O_W2 + (fq + i) * 4);
            wp23[i] = *(const ull*)(s_small + O_W2 + (fq + i) * 4 + 2);
        }
        const float4 b1v = *(const float4*)(s_small + O_B1 + fq);
        const float* S1p = S1 + lh * 4;

        for (int n = wid; n < NN; n += NWARP) {
            const int j0 = s_rp[n], j1 = s_rp[n + 1];
            const int jlast = j1 - 4;
            ull a01 = 0, a23 = 0;
            float2 e0 = __ldg(&g_csr_e[j0 + h]);
            float2 e1 = __ldg(&g_csr_e[j0 + 2 + h]);
            #pragma unroll 1
            for (int j = j0; j < j1; j += 4) {
                const int jn = min(j + 4, jlast);
                const float2 f0 = __ldg(&g_csr_e[jn + h]);
                const float2 f1 = __ldg(&g_csr_e[jn + 2 + h]);
                const ulonglong2 v0 =
                    *(const ulonglong2*)(S1p + __float_as_int(e0.y) * S1S);
                const ulonglong2 v1 =
                    *(const ulonglong2*)(S1p + __float_as_int(e1.y) * S1S);
                const ull w0 = bcast2(e0.x);
                const ull w1 = bcast2(e1.x);
                a01 = ffma2(v0.x, w0, a01);
                a23 = ffma2(v0.y, w0, a23);
                a01 = ffma2(v1.x, w1, a01);
                a23 = ffma2(v1.y, w1, a23);
                e0 = f0; e1 = f1;
            }
            const float2 u0 = unpack2(a01), u1 = unpack2(a23);
            float ax = u0.x, ay = u0.y, az = u1.x, aw = u1.y;
            ax += __shfl_xor_sync(~0u, ax, 16);
            ay += __shfl_xor_sync(~0u, ay, 16);
            az += __shfl_xor_sync(~0u, az, 16);
            aw += __shfl_xor_sync(~0u, aw, 16);
            const float tx = htanh(ax + b1v.x);
            const float ty = htanh(ay + b1v.y);
            const float tz = htanh(az + b1v.z);
            const float tw = htanh(aw + b1v.w);
            ull P01 = 0, P23 = 0;
            {
                const ull btx = bcast2(tx), bty = bcast2(ty);
                const ull btz = bcast2(tz), btw = bcast2(tw);
                P01 = ffma2(btx, wp01[0], P01); P23 = ffma2(btx, wp23[0], P23);
                P01 = ffma2(bty, wp01[1], P01); P23 = ffma2(bty, wp23[1], P23);
                P01 = ffma2(btz, wp01[2], P01); P23 = ffma2(btz, wp23[2], P23);
                P01 = ffma2(btw, wp01[3], P01); P23 = ffma2(btw, wp23[3], P23);
            }
            const float2 q01 = unpack2(P01), q23 = unpack2(P23);
            float4 p = make_float4(q01.x, q01.y, q23.x, q23.y);
            p.x += __shfl_xor_sync(~0u, p.x, 1);
            p.y += __shfl_xor_sync(~0u, p.y, 1);
            p.z += __shfl_xor_sync(~0u, p.z, 1);
            p.w += __shfl_xor_sync(~0u, p.w, 1);
            if (lane < 16 && !(lane & 1))
                *(float4*)(S2 + n * S2S + (lh >> 1) * 4) = p;
        }
    }
    __syncthreads();

    // ========== A2: h2 = tanh(agg(t2)+b2); t3 = h2@W3 -> S1 (t3) =====
    // quarter-warp per edge, depth-2 clamped prefetch
    {
        const int q  = lane >> 3;
        const int lb = lane & 7;
        const float4 b2v = *(const float4*)(s_small + O_B2);
        float w30[4], w31[4];
        #pragma unroll
        for (int f = 0; f < 4; f++) {
            w30[f] = s_small[O_W3 + f * 2 + 0];
            w31[f] = s_small[O_W3 + f * 2 + 1];
        }
        const float* S2p = S2 + lb * 4;
        for (int n = wid; n < NN; n += NWARP) {
            const int j0 = s_rp[n], j1 = s_rp[n + 1];
            const int jlast = j1 - 4;
            ull a01 = 0, a23 = 0;
            float2 e = __ldg(&g_csr_e[j0 + q]);
            float2 f = __ldg(&g_csr_e[min(j0 + 4, jlast) + q]);
            #pragma unroll 1
            for (int j = j0; j < j1; j += 4) {
                const float2 g2 = __ldg(&g_csr_e[min(j + 8, jlast) + q]);
                const ulonglong2 v =
                    *(const ulonglong2*)(S2p + __float_as_int(e.y) * S2S);
                const ull ww = bcast2(e.x);
                a01 = ffma2(v.x, ww, a01);
                a23 = ffma2(v.y, ww, a23);
                e = f; f = g2;
            }
            const float2 u0 = unpack2(a01), u1 = unpack2(a23);
            float ax = u0.x, ay = u0.y, az = u1.x, aw = u1.y;
            #pragma unroll
            for (int off = 8; off <= 16; off <<= 1) {
                ax += __shfl_xor_sync(~0u, ax, off);
                ay += __shfl_xor_sync(~0u, ay, off);
                az += __shfl_xor_sync(~0u, az, off);
                aw += __shfl_xor_sync(~0u, aw, off);
            }
            const float t0 = htanh(ax + b2v.x);
            const float t1 = htanh(ay + b2v.y);
            const float t2 = htanh(az + b2v.z);
            const float t3 = htanh(aw + b2v.w);
            const float p0 = t0 * w30[0] + t1 * w30[1] + t2 * w30[2] + t3 * w30[3];
            const float p1 = t0 * w31[0] + t1 * w31[1] + t2 * w31[2] + t3 * w31[3];
            if (lane < 8)
                *(float2*)(S1 + n * T3S + lb * 2) = make_float2(p0, p1);
        }
    }
    __syncthreads();

    // ========== A3: h3 = agg(t3)+b3 -> xfc-dup[b][2n..] in S2 ========
    // each value written DUPLICATED: (v,v) so FC1 feeds f32x2 directly
    {
        const int o  = lane >> 3;
        const int lb = lane & 7;
        const float b3x = s_small[O_B3 + 0];
        const float b3y = s_small[O_B3 + 1];
        const float* T3p = S1 + lb * 2;
        for (int n = wid; n < NN; n += NWARP) {
            const int j0 = s_rp[n], j1 = s_rp[n + 1];
            const int jlast = j1 - 4;
            float ax = 0.0f, ay = 0.0f;
            float2 e = __ldg(&g_csr_e[j0 + o]);
            float2 f = __ldg(&g_csr_e[min(j0 + 4, jlast) + o]);
            #pragma unroll 1
            for (int j = j0; j < j1; j += 4) {
                const float2 g2 = __ldg(&g_csr_e[min(j + 8, jlast) + o]);
                const float2 v = *(const float2*)(T3p + __float_as_int(e.y) * T3S);
                ax += e.x * v.x;
                ay += e.x * v.y;
                e = f; f = g2;
            }
            #pragma unroll
            for (int off = 8; off <= 16; off <<= 1) {
                ax += __shfl_xor_sync(~0u, ax, off);
                ay += __shfl_xor_sync(~0u, ay, off);
            }
            if (lane < 8) {
                const float rx = ax + b3x, ry = ay + b3y;
                *(float4*)(S2 + lb * XFSD + 4 * n) = make_float4(rx, rx, ry, ry);
            }
        }
        // zero duplicated pad k = 462, 463 (floats 924..927 per graph)
        if (tid < 8)
            *(float4*)(S2 + tid * XFSD + 924) = make_float4(0.f, 0.f, 0.f, 0.f);
    }
    __syncthreads();

    // ========== FC1: xfc[8,464] @ Wf1[462,120] + bf1 -> elu -> S1 ====
    // 480 active: kh (4 k-quarters of 116) x jg (60: 2 j) x bq (2: 4 b)
    // duplicated xfc feeds fma.f32x2 with zero broadcast movs.
    {
        const int kh = tid >> 7;            // 0..3
        const int r  = tid & 127;           // 0..127
        const int jg = r >> 1;              // 0..63 (active < 60)
        const int bq = r & 1;
        const bool active = jg < 60;
        ull accB0 = 0, accB1 = 0, accB2 = 0, accB3 = 0;

        if (active) {
            const int j0 = jg * 2;
            const float* wb = Wf1 + j0;
            const float* xd = S2 + (bq * 4) * XFSD;
            const int k0 = kh * 116;
            #pragma unroll 2
            for (int k = k0; k < k0 + 116; k += 2) {
                const ull w0 = __ldg((const ull*)(wb + (k + 0) * 120));
                const ull w1 = __ldg((const ull*)(wb + (k + 1) * 120));
                const ulonglong2 v0 = *(const ulonglong2*)(xd + 2 * k);
                const ulonglong2 v1 = *(const ulonglong2*)(xd + XFSD + 2 * k);
                const ulonglong2 v2 = *(const ulonglong2*)(xd + 2 * XFSD + 2 * k);
                const ulonglong2 v3 = *(const ulonglong2*)(xd + 3 * XFSD + 2 * k);
                accB0 = ffma2(v0.x, w0, accB0); accB0 = ffma2(v0.y, w1, accB0);
                accB1 = ffma2(v1.x, w0, accB1); accB1 = ffma2(v1.y, w1, accB1);
                accB2 = ffma2(v2.x, w0, accB2); accB2 = ffma2(v2.y, w1, accB2);
                accB3 = ffma2(v3.x, w0, accB3); accB3 = ffma2(v3.y, w1, accB3);
            }
            if (kh > 0) {
                const float2 u0 = unpack2(accB0), u1 = unpack2(accB1);
                const float2 u2 = unpack2(accB2), u3 = unpack2(accB3);
                float* scr = S1 + 4096 + ((kh - 1) * 120 + r) * 8;
                *(float4*)scr       = make_float4(u0.x, u0.y, u1.x, u1.y);
                *(float4*)(scr + 4) = make_float4(u2.x, u2.y, u3.x, u3.y);
            }
        }
        __syncthreads();
        if (active && kh == 0) {
            const int j0 = jg * 2;
            float2 a0 = unpack2(accB0), a1 = unpack2(accB1);
            float2 a2 = unpack2(accB2), a3 = unpack2(accB3);
            #pragma unroll
            for (int p = 0; p < 3; p++) {
                const float* scr = S1 + 4096 + (p * 120 + r) * 8;
                const float4 s0 = *(const float4*)scr;
                const float4 s1 = *(const float4*)(scr + 4);
                a0.x += s0.x; a0.y += s0.y;
                a1.x += s0.z; a1.y += s0.w;
                a2.x += s1.x; a2.y += s1.y;
                a3.x += s1.z; a3.y += s1.w;
            }
            const float bfa = s_small[O_BF1 + j0];
            const float bfb = s_small[O_BF1 + j0 + 1];
            const int bb = bq * 4;
            S1[(bb + 0) * H1S + j0]     = elu1(a0.x + bfa);
            S1[(bb + 0) * H1S + j0 + 1] = elu1(a0.y + bfb);
            S1[(bb + 1) * H1S + j0]     = elu1(a1.x + bfa);
            S1[(bb + 1) * H1S + j0 + 1] = elu1(a1.y + bfb);
            S1[(bb + 2) * H1S + j0]     = elu1(a2.x + bfa);
            S1[(bb + 2) * H1S + j0 + 1] = elu1(a2.y + bfb);
            S1[(bb + 3) * H1S + j0]     = elu1(a3.x + bfa);
            S1[(bb + 3) * H1S + j0 + 1] = elu1(a3.y + bfb);
        }
    }
    __syncthreads();

    // ========== FC2: h1[8,120] @ Wf2[120,84] + bf2 -> elu -> S2 ======
    if (tid < 336) {
        const int b = tid & 7, jg = tid >> 3;   // jg 0..41
        const int j0 = jg * 2;
        float2 acc = make_float2(s_small[O_BF2 + j0], s_small[O_BF2 + j0 + 1]);
        const float* xin = S1 + b * H1S;
        const float* wb  = Wf2 + j0;
        #pragma unroll 2
        for (int k = 0; k < 120; k += 4) {
            const float4 v  = *(const float4*)(xin + k);
            const float2 w0 = __ldg((const float2*)(wb + (k + 0) * 84));
            const float2 w1 = __ldg((const float2*)(wb + (k + 1) * 84));
            const float2 w2 = __ldg((const float2*)(wb + (k + 2) * 84));
            const float2 w3 = __ldg((const float2*)(wb + (k + 3) * 84));
            acc.x += v.x * w0.x + v.y * w1.x + v.z * w2.x + v.w * w3.x;
            acc.y += v.x * w0.y + v.y * w1.y + v.z * w2.y + v.w * w3.y;
        }
        S2[b * H2S + j0 + 0] = elu1(acc.x);
        S2[b * H2S + j0 + 1] = elu1(acc.y);
    }
    __syncthreads();

    // ========== FC3: h2[8,84] @ Wf3[84,10] + bf3 -> out ==============
    if (tid < 80) {
        const int b = tid & 7, j = tid >> 3;    // j 0..9
        float acc = s_small[O_BF3 + j];
        const float* xin = S2 + b * H2S;
        #pragma unroll 3
        for (int k = 0; k < 84; k += 4) {
            const float4 v = *(const float4*)(xin + k);
            acc += v.x * __ldg(Wf3 + (k + 0) * 10 + j);
            acc += v.y * __ldg(Wf3 + (k + 1) * 10 + j);
            acc += v.z * __ldg(Wf3 + (k + 2) * 10 + j);
            acc += v.w * __ldg(Wf3 + (k + 3) * 10 + j);
        }
        const int g = b0 + b;
        if (g < B) out[(size_t)g * 10 + j] = acc;
    }
}

// =====================================================================
extern "C" void kernel_launch(void* const* d_in, const int* in_sizes, int n_in,
                              void* d_out, int out_size) {
    const float* x   = (const float*)d_in[0];
    const void*  ei  = d_in[1];
    const float* W1  = (const float*)d_in[2];
    const float* b1  = (const float*)d_in[3];
    const float* W2  = (const float*)d_in[4];
    const float* b2  = (const float*)d_in[5];
    const float* W3  = (const float*)d_in[6];
    const float* b3  = (const float*)d_in[7];
    const float* Wf1 = (const float*)d_in[8];
    const float* bf1 = (const float*)d_in[9];
    const float* Wf2 = (const float*)d_in[10];
    const float* bf2 = (const float*)d_in[11];
    const float* Wf3 = (const float*)d_in[12];
    const float* bf3 = (const float*)d_in[13];
    float* out = (float*)d_out;

    const int B = in_sizes[0] / (NN * 12);
    const int E = in_sizes[1] / 2;

    prep_kernel<<<1, 256>>>(ei, E);

    static int smem_set = 0;
    if (!smem_set) {
        cudaFuncSetAttribute(gcn_fused_kernel,
                             cudaFuncAttributeMaxDynamicSharedMemorySize,
                             SM_BYTES);
        smem_set = 1;
    }

    const int blocks = (B + BT - 1) / BT;
    gcn_fused_kernel<<<blocks, THREADS, SM_BYTES>>>(
        x, W1, b1, W2, b2, W3, b3, Wf1, bf1, Wf2, bf2, Wf3, bf3,
        out, B);
}

// round 14
// speedup vs baseline: 1.1734x; 1.1734x over previous
#include <cuda_runtime.h>
#include <math.h>

#define NN 231
#define BT 8
#define THREADS 512
#define NWARP 16
#define MAXM 4096     // padded-to-4 edges <= 231*4 + 2079 ~ 3003

#define S1S 68    // t1 row stride: 64 data + 4 (bank rotate, 16B aligned)
#define S2S 36    // t2 row stride: 32 + 4
#define T3S 20    // t3 row stride: 16 + 4
#define XFS 476   // FC input stride per graph
#define H1S 124   // FC1 out stride
#define H2S 92    // FC2 out stride

typedef unsigned long long ull;

// ---------------- persistent CSR built by prep kernel ----------------
__device__ int    g_row_ptr[NN + 1];
__device__ float2 g_csr_e[MAXM];    // (w, src-as-float-bits)

// =====================================================================
// Prep: deterministic CSR (stable counting sort by dst); each row padded
// to a multiple of 4 with (w=0, src=0) dummies.
// =====================================================================
__global__ void prep_kernel(const void* __restrict__ ei, int E) {
    __shared__ short s_src[2304];
    __shared__ short s_dst[2304];
    __shared__ int   deg[NN];
    __shared__ int   pdeg[NN];
    __shared__ int   rp[NN + 1];
    __shared__ float inv[NN];
    __shared__ int   cnt[32][NN];
    __shared__ int   is64;

    const int tid = threadIdx.x;
    const int M = E + NN;

    if (tid == 0) {
        const long long* p = (const long long*)ei;
        int ok = 1;
        for (int i = 0; i < 8; i++) {
            long long v = p[i];
            if (v < 0 || v >= NN) ok = 0;
        }
        is64 = ok;
    }
    for (int n = tid; n < NN; n += blockDim.x) deg[n] = 0;
    __syncthreads();

    for (int e = tid; e < M; e += blockDim.x) {
        int s, d;
        if (e < E) {
            if (is64) {
                s = (int)((const long long*)ei)[e];
                d = (int)((const long long*)ei)[E + e];
            } else {
                s = ((const int*)ei)[e];
                d = ((const int*)ei)[E + e];
            }
        } else {
            s = d = e - E;   // self loops appended after real edges
        }
        s_src[e] = (short)s;
        s_dst[e] = (short)d;
        atomicAdd(&deg[d], 1);
    }
    __syncthreads();

    for (int n = tid; n < NN; n += blockDim.x) {
        inv[n]  = rsqrtf((float)max(deg[n], 1));
        pdeg[n] = (deg[n] + 3) & ~3;
    }
    __syncthreads();
    if (tid == 0) {
        int acc = 0;
        for (int n = 0; n < NN; n++) { rp[n] = acc; acc += pdeg[n]; }
        rp[NN] = acc;
    }
    for (int i = tid; i < 32 * NN; i += blockDim.x)
        ((int*)cnt)[i] = 0;
    __syncthreads();

    const int chunk = (M + 31) / 32;
    if (tid < 32) {
        int e0 = tid * chunk, e1 = min(e0 + chunk, M);
        for (int e = e0; e < e1; e++) cnt[tid][s_dst[e]]++;
    }
    __syncthreads();

    for (int n = tid; n < NN; n += blockDim.x) {
        int run = rp[n];
        for (int t = 0; t < 32; t++) {
            int c = cnt[t][n];
            cnt[t][n] = run;
            run += c;
        }
    }
    __syncthreads();

    if (tid < 32) {
        int e0 = tid * chunk, e1 = min(e0 + chunk, M);
        for (int e = e0; e < e1; e++) {
            int d = s_dst[e], s = s_src[e];
            int pos = cnt[tid][d]++;
            g_csr_e[pos] = make_float2(inv[s] * inv[d], __int_as_float(s));
        }
    }
    __syncthreads();

    // pad rows with dummy edges (w=0, src=0)
    for (int n = tid; n < NN; n += blockDim.x) {
        for (int p = deg[n]; p < pdeg[n]; p++)
            g_csr_e[rp[n] + p] = make_float2(0.0f, __int_as_float(0));
    }
    for (int n = tid; n <= NN; n += blockDim.x) g_row_ptr[n] = rp[n];
}

// =====================================================================
__device__ __forceinline__ float htanh(float x) {
    float y;
    asm("tanh.approx.f32 %0, %1;" : "=f"(y) : "f"(x));
    return y;
}
__device__ __forceinline__ float elu1(float v) {
    return v > 0.0f ? v : (__expf(v) - 1.0f);
}
__device__ __forceinline__ ull ffma2(ull a, ull b, ull c) {
    ull d;
    asm("fma.rn.f32x2 %0, %1, %2, %3;" : "=l"(d) : "l"(a), "l"(b), "l"(c));
    return d;
}
__device__ __forceinline__ ull bcast2(float x) {
    ull d;
    asm("mov.b64 %0, {%1, %1};" : "=l"(d) : "r"(__float_as_uint(x)));
    return d;
}
__device__ __forceinline__ float2 unpack2(ull d) {
    unsigned int lo, hi;
    asm("mov.b64 {%0, %1}, %2;" : "=r"(lo), "=r"(hi) : "l"(d));
    return make_float2(__int_as_float(lo), __int_as_float(hi));
}

// small-weight shared offsets (floats)
#define O_B1  96     // 8
#define O_W2  104    // 8x4
#define O_B2  136    // 4
#define O_W3  140    // 4x2
#define O_B3  148    // 2
#define O_BF1 152    // 120
#define O_BF2 272    // 84
#define O_BF3 356    // 10
#define SMALLSZ 384

#define SM_FLOATS (NN*S1S + NN*S2S + SMALLSZ)
#define SM_BYTES  (SM_FLOATS*4 + (NN+1)*4)

__global__ void __launch_bounds__(THREADS, 2)
gcn_fused_kernel(const float* __restrict__ x,
                 const float* __restrict__ W1, const float* __restrict__ b1,
                 const float* __restrict__ W2, const float* __restrict__ b2,
                 const float* __restrict__ W3, const float* __restrict__ b3,
                 const float* __restrict__ Wf1, const float* __restrict__ bf1,
                 const float* __restrict__ Wf2, const float* __restrict__ bf2,
                 const float* __restrict__ Wf3, const float* __restrict__ bf3,
                 float* __restrict__ out, int B) {
    extern __shared__ float sm[];
    float*  S1      = sm;                  // t1 [n][b8][f8], stride 68
    float*  S2      = S1 + NN * S1S;       // t2 [n][b8][f4], stride 36
    float*  s_small = S2 + NN * S2S;
    int*    s_rp    = (int*)(s_small + SMALLSZ);

    const int tid  = threadIdx.x;
    const int wid  = tid >> 5;
    const int lane = tid & 31;
    const int b0   = blockIdx.x * BT;

    // ---- stage rp + small weights (no barrier needed before T1:
    //      T1 reads only global memory; barrier after T1 publishes all) --
    for (int i = tid; i <= NN; i += THREADS) s_rp[i] = g_row_ptr[i];
    for (int i = tid; i < 8;   i += THREADS) s_small[O_B1 + i] = b1[i];
    for (int i = tid; i < 32;  i += THREADS) s_small[O_W2 + i] = W2[i];
    for (int i = tid; i < 4;   i += THREADS) s_small[O_B2 + i] = b2[i];
    for (int i = tid; i < 8;   i += THREADS) s_small[O_W3 + i] = W3[i];
    for (int i = tid; i < 2;   i += THREADS) s_small[O_B3 + i] = b3[i];
    for (int i = tid; i < 120; i += THREADS) s_small[O_BF1 + i] = bf1[i];
    for (int i = tid; i < 84;  i += THREADS) s_small[O_BF2 + i] = bf2[i];
    for (int i = tid; i < 10;  i += THREADS) s_small[O_BF3 + i] = bf3[i];

    // ========== T1: t1 = x @ W1 -> S1[n][b][f]  (W1 via __ldg) =======
    for (int idx = tid; idx < NN * BT; idx += THREADS) {
        const int b = idx / NN, n = idx - b * NN;
        const int g = b0 + b;
        float xa[12];
        if (g < B) {
            const float4* xp = (const float4*)(x + ((size_t)g * NN + n) * 12);
            float4 v0 = __ldg(xp), v1 = __ldg(xp + 1), v2 = __ldg(xp + 2);
            xa[0] = v0.x; xa[1] = v0.y; xa[2]  = v0.z; xa[3]  = v0.w;
            xa[4] = v1.x; xa[5] = v1.y; xa[6]  = v1.z; xa[7]  = v1.w;
            xa[8] = v2.x; xa[9] = v2.y; xa[10] = v2.z; xa[11] = v2.w;
        } else {
            #pragma unroll
            for (int c = 0; c < 12; c++) xa[c] = 0.0f;
        }
        ull p0 = 0, p1 = 0, p2 = 0, p3 = 0;
        #pragma unroll
        for (int c = 0; c < 12; c++) {
            const ull xb = bcast2(xa[c]);
            const ull* wrow = (const ull*)(W1 + c * 8);
            p0 = ffma2(xb, __ldg(wrow + 0), p0);
            p1 = ffma2(xb, __ldg(wrow + 1), p1);
            p2 = ffma2(xb, __ldg(wrow + 2), p2);
            p3 = ffma2(xb, __ldg(wrow + 3), p3);
        }
        float* dst = S1 + n * S1S + b * 8;
        *(ulonglong2*)dst       = make_ulonglong2(p0, p1);
        *(ulonglong2*)(dst + 4) = make_ulonglong2(p2, p3);
    }
    __syncthreads();

    // ========== A1: h1 = tanh(agg(t1)+b1); t2 = h1@W2 -> S2 ==========
    // half-warp per edge, 2 edges per lane per iter, SW-pipelined edge
    // prefetch; lh owns float4: b = lh>>1, fq = (lh&1)*4
    {
        const int h  = lane >> 4;
        const int lh = lane & 15;
        const int fq = (lh & 1) * 4;
        float w2r[4][4];
        #pragma unroll
        for (int i = 0; i < 4; i++)
            #pragma unroll
            for (int f2 = 0; f2 < 4; f2++)
                w2r[i][f2] = s_small[O_W2 + (fq + i) * 4 + f2];
        const float4 b1v = *(const float4*)(s_small + O_B1 + fq);
        const float* S1p = S1 + lh * 4;

        for (int n = wid; n < NN; n += NWARP) {
            const int j0 = s_rp[n], j1 = s_rp[n + 1];
            ull a01 = 0, a23 = 0;
            float2 e0 = __ldg(&g_csr_e[j0 + h]);
            float2 e1 = __ldg(&g_csr_e[j0 + 2 + h]);
            int j = j0;
            #pragma unroll 1
            for (; j + 4 < j1; j += 4) {
                const float2 f0 = __ldg(&g_csr_e[j + 4 + h]);
                const float2 f1 = __ldg(&g_csr_e[j + 6 + h]);
                const ulonglong2 v0 =
                    *(const ulonglong2*)(S1p + __float_as_int(e0.y) * S1S);
                const ulonglong2 v1 =
                    *(const ulonglong2*)(S1p + __float_as_int(e1.y) * S1S);
                const ull w0 = bcast2(e0.x);
                const ull w1 = bcast2(e1.x);
                a01 = ffma2(v0.x, w0, a01);
                a23 = ffma2(v0.y, w0, a23);
                a01 = ffma2(v1.x, w1, a01);
                a23 = ffma2(v1.y, w1, a23);
                e0 = f0; e1 = f1;
            }
            {   // tail (last 4 edges)
                const ulonglong2 v0 =
                    *(const ulonglong2*)(S1p + __float_as_int(e0.y) * S1S);
                const ulonglong2 v1 =
                    *(const ulonglong2*)(S1p + __float_as_int(e1.y) * S1S);
                const ull w0 = bcast2(e0.x);
                const ull w1 = bcast2(e1.x);
                a01 = ffma2(v0.x, w0, a01);
                a23 = ffma2(v0.y, w0, a23);
                a01 = ffma2(v1.x, w1, a01);
                a23 = ffma2(v1.y, w1, a23);
            }
            const float2 u0 = unpack2(a01), u1 = unpack2(a23);
            float ax = u0.x, ay = u0.y, az = u1.x, aw = u1.y;
            ax += __shfl_xor_sync(~0u, ax, 16);
            ay += __shfl_xor_sync(~0u, ay, 16);
            az += __shfl_xor_sync(~0u, az, 16);
            aw += __shfl_xor_sync(~0u, aw, 16);
            const float tx = htanh(ax + b1v.x);
            const float ty = htanh(ay + b1v.y);
            const float tz = htanh(az + b1v.z);
            const float tw = htanh(aw + b1v.w);
            float4 p;
            p.x = tx * w2r[0][0] + ty * w2r[1][0] + tz * w2r[2][0] + tw * w2r[3][0];
            p.y = tx * w2r[0][1] + ty * w2r[1][1] + tz * w2r[2][1] + tw * w2r[3][1];
            p.z = tx * w2r[0][2] + ty * w2r[1][2] + tz * w2r[2][2] + tw * w2r[3][2];
            p.w = tx * w2r[0][3] + ty * w2r[1][3] + tz * w2r[2][3] + tw * w2r[3][3];
            p.x += __shfl_xor_sync(~0u, p.x, 1);
            p.y += __shfl_xor_sync(~0u, p.y, 1);
            p.z += __shfl_xor_sync(~0u, p.z, 1);
            p.w += __shfl_xor_sync(~0u, p.w, 1);
            if (lane < 16 && !(lane & 1))
                *(float4*)(S2 + n * S2S + (lh >> 1) * 4) = p;
        }
    }
    __syncthreads();

    // ========== A2: h2 = tanh(agg(t2)+b2); t3 = h2@W3 -> S1 (t3) =====
    // quarter-warp per edge; lb owns float4, SW-pipelined edge prefetch
    {
        const int q  = lane >> 3;
        const int lb = lane & 7;
        const float4 b2v = *(const float4*)(s_small + O_B2);
        float w30[4], w31[4];
        #pragma unroll
        for (int f = 0; f < 4; f++) {
            w30[f] = s_small[O_W3 + f * 2 + 0];
            w31[f] = s_small[O_W3 + f * 2 + 1];
        }
        const float* S2p = S2 + lb * 4;
        for (int n = wid; n < NN; n += NWARP) {
            const int j0 = s_rp[n], j1 = s_rp[n + 1];
            ull a01 = 0, a23 = 0;
            float2 e = __ldg(&g_csr_e[j0 + q]);
            int j = j0;
            #pragma unroll 1
            for (; j + 4 < j1; j += 4) {
                const float2 f = __ldg(&g_csr_e[j + 4 + q]);
                const ulonglong2 v =
                    *(const ulonglong2*)(S2p + __float_as_int(e.y) * S2S);
                const ull ww = bcast2(e.x);
                a01 = ffma2(v.x, ww, a01);
                a23 = ffma2(v.y, ww, a23);
                e = f;
            }
            {   // tail
                const ulonglong2 v =
                    *(const ulonglong2*)(S2p + __float_as_int(e.y) * S2S);
                const ull ww = bcast2(e.x);
                a01 = ffma2(v.x, ww, a01);
                a23 = ffma2(v.y, ww, a23);
            }
            const float2 u0 = unpack2(a01), u1 = unpack2(a23);
            float ax = u0.x, ay = u0.y, az = u1.x, aw = u1.y;
            #pragma unroll
            for (int off = 8; off <= 16; off <<= 1) {
                ax += __shfl_xor_sync(~0u, ax, off);
                ay += __shfl_xor_sync(~0u, ay, off);
                az += __shfl_xor_sync(~0u, az, off);
                aw += __shfl_xor_sync(~0u, aw, off);
            }
            const float t0 = htanh(ax + b2v.x);
            const float t1 = htanh(ay + b2v.y);
            const float t2 = htanh(az + b2v.z);
            const float t3 = htanh(aw + b2v.w);
            const float p0 = t0 * w30[0] + t1 * w30[1] + t2 * w30[2] + t3 * w30[3];
            const float p1 = t0 * w31[0] + t1 * w31[1] + t2 * w31[2] + t3 * w31[3];
            if (lane < 8)
                *(float2*)(S1 + n * T3S + lb * 2) = make_float2(p0, p1);
        }
    }
    __syncthreads();

    // ========== A3: h3 = agg(t3)+b3 -> xfc[b][2n+c] in S2 ============
    {
        const int o  = lane >> 3;
        const int lb = lane & 7;
        const float b3x = s_small[O_B3 + 0];
        const float b3y = s_small[O_B3 + 1];
        const float* T3p = S1 + lb * 2;
        for (int n = wid; n < NN; n += NWARP) {
            const int j0 = s_rp[n], j1 = s_rp[n + 1];
            float ax = 0.0f, ay = 0.0f;
            float2 e = __ldg(&g_csr_e[j0 + o]);
            int j = j0;
            #pragma unroll 1
            for (; j + 4 < j1; j += 4) {
                const float2 f = __ldg(&g_csr_e[j + 4 + o]);
                const float2 v = *(const float2*)(T3p + __float_as_int(e.y) * T3S);
                ax += e.x * v.x;
                ay += e.x * v.y;
                e = f;
            }
            {   // tail
                const float2 v = *(const float2*)(T3p + __float_as_int(e.y) * T3S);
                ax += e.x * v.x;
                ay += e.x * v.y;
            }
            #pragma unroll
            for (int off = 8; off <= 16; off <<= 1) {
                ax += __shfl_xor_sync(~0u, ax, off);
                ay += __shfl_xor_sync(~0u, ay, off);
            }
            if (lane < 8)
                *(float2*)(S2 + lb * XFS + 2 * n) = make_float2(ax + b3x, ay + b3y);
        }
        // zero xfc pad k = 462, 463 (read by the padded FC1 loop)
        if (tid < 16)
            S2[(tid >> 1) * XFS + 462 + (tid & 1)] = 0.0f;
    }
    __syncthreads();

    // ========== FC1: xfc[8,464] @ Wf1[462,120] + bf1 -> elu -> S1 ====
    // 480 active threads: kh (4 k-quarters of 116) x jg (60: 2 j) x bq (2: 4 b)
    {
        const int kh = tid >> 7;            // 0..3
        const int r  = tid & 127;           // 0..127
        const int jg = r >> 1;              // 0..63 (active < 60)
        const int bq = r & 1;
        const bool active = jg < 60;
        float acc[2][4];
        #pragma unroll
        for (int j = 0; j < 2; j++)
            #pragma unroll
            for (int i = 0; i < 4; i++) acc[j][i] = 0.0f;

        if (active) {
            const int j0 = jg * 2;
            const float* wb = Wf1 + j0;
            const float* x0 = S2 + (bq * 4 + 0) * XFS;
            const float* x1 = S2 + (bq * 4 + 1) * XFS;
            const float* x2 = S2 + (bq * 4 + 2) * XFS;
            const float* x3 = S2 + (bq * 4 + 3) * XFS;
            const int k0 = kh * 116;
            #pragma unroll 1
            for (int k = k0; k < k0 + 116; k += 4) {
                const float4 a0 = *(const float4*)(x0 + k);
                const float4 a1 = *(const float4*)(x1 + k);
                const float4 a2 = *(const float4*)(x2 + k);
                const float4 a3 = *(const float4*)(x3 + k);
                const float2 w0 = __ldg((const float2*)(wb + (k + 0) * 120));
                const float2 w1 = __ldg((const float2*)(wb + (k + 1) * 120));
                const float2 w2 = __ldg((const float2*)(wb + (k + 2) * 120));
                const float2 w3 = __ldg((const float2*)(wb + (k + 3) * 120));
                acc[0][0] += a0.x * w0.x + a0.y * w1.x + a0.z * w2.x + a0.w * w3.x;
                acc[1][0] += a0.x * w0.y + a0.y * w1.y + a0.z * w2.y + a0.w * w3.y;
                acc[0][1] += a1.x * w0.x + a1.y * w1.x + a1.z * w2.x + a1.w * w3.x;
                acc[1][1] += a1.x * w0.y + a1.y * w1.y + a1.z * w2.y + a1.w * w3.y;
                acc[0][2] += a2.x * w0.x + a2.y * w1.x + a2.z * w2.x + a2.w * w3.x;
                acc[1][2] += a2.x * w0.y + a2.y * w1.y + a2.z * w2.y + a2.w * w3.y;
                acc[0][3] += a3.x * w0.x + a3.y * w1.x + a3.z * w2.x + a3.w * w3.x;
                acc[1][3] += a3.x * w0.y + a3.y * w1.y + a3.z * w2.y + a3.w * w3.y;
            }
            if (kh > 0) {
                // write partials to dead S1 scratch (beyond h1 region)
                float* scr = S1 + 4096 + ((kh - 1) * 120 + r) * 8;
                *(float4*)scr = make_float4(acc[0][0], acc[1][0], acc[0][1], acc[1][1]);
                *(float4*)(scr + 4) = make_float4(acc[0][2], acc[1][2], acc[0][3], acc[1][3]);
            }
        }
        __syncthreads();
        if (active && kh == 0) {
            const int j0 = jg * 2;
            const float bfa = s_small[O_BF1 + j0];
            const float bfb = s_small[O_BF1 + j0 + 1];
            #pragma unroll
            for (int p = 0; p < 3; p++) {
                const float* scr = S1 + 4096 + (p * 120 + r) * 8;
                const float4 s0 = *(const float4*)scr;
                const float4 s1 = *(const float4*)(scr + 4);
                acc[0][0] += s0.x; acc[1][0] += s0.y;
                acc[0][1] += s0.z; acc[1][1] += s0.w;
                acc[0][2] += s1.x; acc[1][2] += s1.y;
                acc[0][3] += s1.z; acc[1][3] += s1.w;
            }
            const int bb = bq * 4;
            S1[(bb + 0) * H1S + j0]     = elu1(acc[0][0] + bfa);
            S1[(bb + 0) * H1S + j0 + 1] = elu1(acc[1][0] + bfb);
            S1[(bb + 1) * H1S + j0]     = elu1(acc[0][1] + bfa);
            S1[(bb + 1) * H1S + j0 + 1] = elu1(acc[1][1] + bfb);
            S1[(bb + 2) * H1S + j0]     = elu1(acc[0][2] + bfa);
            S1[(bb + 2) * H1S + j0 + 1] = elu1(acc[1][2] + bfb);
            S1[(bb + 3) * H1S + j0]     = elu1(acc[0][3] + bfa);
            S1[(bb + 3) * H1S + j0 + 1] = elu1(acc[1][3] + bfb);
        }
    }
    __syncthreads();

    // ========== FC2: h1[8,120] @ Wf2[120,84] + bf2 -> elu -> S2 ======
    if (tid < 336) {
        const int b = tid & 7, jg = tid >> 3;   // jg 0..41
        const int j0 = jg * 2;
        float2 acc = make_float2(s_small[O_BF2 + j0], s_small[O_BF2 + j0 + 1]);
        const float* xin = S1 + b * H1S;
        const float* wb  = Wf2 + j0;
        #pragma unroll 2
        for (int k = 0; k < 120; k += 4) {
            const float4 v  = *(const float4*)(xin + k);
            const float2 w0 = __ldg((const float2*)(wb + (k + 0) * 84));
            const float2 w1 = __ldg((const float2*)(wb + (k + 1) * 84));
            const float2 w2 = __ldg((const float2*)(wb + (k + 2) * 84));
            const float2 w3 = __ldg((const float2*)(wb + (k + 3) * 84));
            acc.x += v.x * w0.x + v.y * w1.x + v.z * w2.x + v.w * w3.x;
            acc.y += v.x * w0.y + v.y * w1.y + v.z * w2.y + v.w * w3.y;
        }
        S2[b * H2S + j0 + 0] = elu1(acc.x);
        S2[b * H2S + j0 + 1] = elu1(acc.y);
    }
    __syncthreads();

    // ========== FC3: h2[8,84] @ Wf3[84,10] + bf3 -> out ==============
    if (tid < 80) {
        const int b = tid & 7, j = tid >> 3;    // j 0..9
        float acc = s_small[O_BF3 + j];
        const float* xin = S2 + b * H2S;
        #pragma unroll 3
        for (int k = 0; k < 84; k += 4) {
            const float4 v = *(const float4*)(xin + k);
            acc += v.x * __ldg(Wf3 + (k + 0) * 10 + j);
            acc += v.y * __ldg(Wf3 + (k + 1) * 10 + j);
            acc += v.z * __ldg(Wf3 + (k + 2) * 10 + j);
            acc += v.w * __ldg(Wf3 + (k + 3) * 10 + j);
        }
        const int g = b0 + b;
        if (g < B) out[(size_t)g * 10 + j] = acc;
    }
}

// =====================================================================
extern "C" void kernel_launch(void* const* d_in, const int* in_sizes, int n_in,
                              void* d_out, int out_size) {
    const float* x   = (const float*)d_in[0];
    const void*  ei  = d_in[1];
    const float* W1  = (const float*)d_in[2];
    const float* b1  = (const float*)d_in[3];
    const float* W2  = (const float*)d_in[4];
    const float* b2  = (const float*)d_in[5];
    const float* W3  = (const float*)d_in[6];
    const float* b3  = (const float*)d_in[7];
    const float* Wf1 = (const float*)d_in[8];
    const float* bf1 = (const float*)d_in[9];
    const float* Wf2 = (const float*)d_in[10];
    const float* bf2 = (const float*)d_in[11];
    const float* Wf3 = (const float*)d_in[12];
    const float* bf3 = (const float*)d_in[13];
    float* out = (float*)d_out;

    const int B = in_sizes[0] / (NN * 12);
    const int E = in_sizes[1] / 2;

    prep_kernel<<<1, 256>>>(ei, E);

    static int smem_set = 0;
    if (!smem_set) {
        cudaFuncSetAttribute(gcn_fused_kernel,
                             cudaFuncAttributeMaxDynamicSharedMemorySize,
                             SM_BYTES);
        smem_set = 1;
    }

    const int blocks = (B + BT - 1) / BT;
    gcn_fused_kernel<<<blocks, THREADS, SM_BYTES>>>(
        x, W1, b1, W2, b2, W3, b3, Wf1, bf1, Wf2, bf2, Wf3, bf3,
        out, B);
}

// round 15
// speedup vs baseline: 1.2991x; 1.1071x over previous
#include <cuda_runtime.h>
#include <math.h>

#define NN 231
#define BT 8
#define THREADS 512
#define NWARP 16
#define MAXM 4096     // padded-to-4 edges <= 231*4 + 2079 ~ 3003

#define S1S 68    // t1 row stride: 64 data + 4 (bank rotate, 16B aligned)
#define S2S 36    // t2 row stride: 32 + 4
#define T3S 20    // t3 row stride: 16 + 4
#define XFS 476   // FC input stride per graph
#define H1S 124   // FC1 out stride
#define H2S 92    // FC2 out stride

typedef unsigned long long ull;

// ---------------- persistent CSR built by prep kernel ----------------
__device__ int    g_row_ptr[NN + 1];
__device__ float2 g_csr_e[MAXM];    // (w, src-as-float-bits)

// =====================================================================
// Prep: deterministic CSR (stable counting sort by dst); each row padded
// to a multiple of 4 with (w=0, src=0) dummies.  Row-pointer build uses
// a parallel 2-level shuffle scan (output identical to the serial scan).
// =====================================================================
__global__ void prep_kernel(const void* __restrict__ ei, int E) {
    __shared__ short s_src[2304];
    __shared__ short s_dst[2304];
    __shared__ int   deg[NN];
    __shared__ int   pdeg[NN];
    __shared__ int   rp[NN + 1];
    __shared__ float inv[NN];
    __shared__ int   cnt[32][NN];
    __shared__ int   wsum[8];
    __shared__ int   is64;

    const int tid = threadIdx.x;
    const int M = E + NN;

    if (tid == 0) {
        const long long* p = (const long long*)ei;
        int ok = 1;
        for (int i = 0; i < 8; i++) {
            long long v = p[i];
            if (v < 0 || v >= NN) ok = 0;
        }
        is64 = ok;
    }
    for (int n = tid; n < NN; n += blockDim.x) deg[n] = 0;
    __syncthreads();

    for (int e = tid; e < M; e += blockDim.x) {
        int s, d;
        if (e < E) {
            if (is64) {
                s = (int)((const long long*)ei)[e];
                d = (int)((const long long*)ei)[E + e];
            } else {
                s = ((const int*)ei)[e];
                d = ((const int*)ei)[E + e];
            }
        } else {
            s = d = e - E;   // self loops appended after real edges
        }
        s_src[e] = (short)s;
        s_dst[e] = (short)d;
        atomicAdd(&deg[d], 1);
    }
    __syncthreads();

    for (int n = tid; n < NN; n += blockDim.x) {
        inv[n]  = rsqrtf((float)max(deg[n], 1));
        pdeg[n] = (deg[n] + 3) & ~3;
    }
    __syncthreads();

    // ---- parallel exclusive scan of pdeg -> rp (2-level shuffle) ----
    {
        const int lane = tid & 31, w = tid >> 5;   // 8 warps of 32
        const int v = (tid < NN) ? pdeg[tid] : 0;
        int inc = v;
        #pragma unroll
        for (int off = 1; off < 32; off <<= 1) {
            int t = __shfl_up_sync(~0u, inc, off);
            if (lane >= off) inc += t;
        }
        if (lane == 31) wsum[w] = inc;
        __syncthreads();
        if (tid < 8) {
            int s = wsum[tid];
            #pragma unroll
            for (int off = 1; off < 8; off <<= 1) {
                int t = __shfl_up_sync(0xffu, s, off);
                if ((int)tid >= off) s += t;
            }
            wsum[tid] = s;
        }
        __syncthreads();
        const int base = (w > 0) ? wsum[w - 1] : 0;
        if (tid < NN) rp[tid] = base + inc - v;
        if (tid == NN - 1) rp[NN] = base + inc;
    }
    for (int i = tid; i < 32 * NN; i += blockDim.x)
        ((int*)cnt)[i] = 0;
    __syncthreads();

    const int chunk = (M + 31) / 32;
    if (tid < 32) {
        int e0 = tid * chunk, e1 = min(e0 + chunk, M);
        for (int e = e0; e < e1; e++) cnt[tid][s_dst[e]]++;
    }
    __syncthreads();

    for (int n = tid; n < NN; n += blockDim.x) {
        int run = rp[n];
        for (int t = 0; t < 32; t++) {
            int c = cnt[t][n];
            cnt[t][n] = run;
            run += c;
        }
    }
    __syncthreads();

    if (tid < 32) {
        int e0 = tid * chunk, e1 = min(e0 + chunk, M);
        for (int e = e0; e < e1; e++) {
            int d = s_dst[e], s = s_src[e];
            int pos = cnt[tid][d]++;
            g_csr_e[pos] = make_float2(inv[s] * inv[d], __int_as_float(s));
        }
    }
    __syncthreads();

    // pad rows with dummy edges (w=0, src=0)
    for (int n = tid; n < NN; n += blockDim.x) {
        for (int p = deg[n]; p < pdeg[n]; p++)
            g_csr_e[rp[n] + p] = make_float2(0.0f, __int_as_float(0));
    }
    for (int n = tid; n <= NN; n += blockDim.x) g_row_ptr[n] = rp[n];
}

// =====================================================================
__device__ __forceinline__ float htanh(float x) {
    float y;
    asm("tanh.approx.f32 %0, %1;" : "=f"(y) : "f"(x));
    return y;
}
__device__ __forceinline__ float elu1(float v) {
    return v > 0.0f ? v : (__expf(v) - 1.0f);
}
__device__ __forceinline__ ull ffma2(ull a, ull b, ull c) {
    ull d;
    asm("fma.rn.f32x2 %0, %1, %2, %3;" : "=l"(d) : "l"(a), "l"(b), "l"(c));
    return d;
}
__device__ __forceinline__ ull bcast2(float x) {
    ull d;
    asm("mov.b64 %0, {%1, %1};" : "=l"(d) : "r"(__float_as_uint(x)));
    return d;
}
__device__ __forceinline__ float2 unpack2(ull d) {
    unsigned int lo, hi;
    asm("mov.b64 {%0, %1}, %2;" : "=r"(lo), "=r"(hi) : "l"(d));
    return make_float2(__int_as_float(lo), __int_as_float(hi));
}

// small-weight shared offsets (floats)
#define O_W1  0      // 12x8
#define O_B1  96     // 8
#define O_W2  104    // 8x4
#define O_B2  136    // 4
#define O_W3  140    // 4x2
#define O_B3  148    // 2
#define O_BF1 152    // 120
#define O_BF2 272    // 84
#define O_BF3 356    // 10
#define SMALLSZ 384

#define SM_FLOATS (NN*S1S + NN*S2S + SMALLSZ)
#define SM_BYTES  (SM_FLOATS*4 + (NN+1)*4)

__global__ void __launch_bounds__(THREADS, 2)
gcn_fused_kernel(const float* __restrict__ x,
                 const float* __restrict__ W1, const float* __restrict__ b1,
                 const float* __restrict__ W2, const float* __restrict__ b2,
                 const float* __restrict__ W3, const float* __restrict__ b3,
                 const float* __restrict__ Wf1, const float* __restrict__ bf1,
                 const float* __restrict__ Wf2, const float* __restrict__ bf2,
                 const float* __restrict__ Wf3, const float* __restrict__ bf3,
                 float* __restrict__ out, int B) {
    extern __shared__ float sm[];
    float*  S1      = sm;                  // t1 [n][b8][f8], stride 68
    float*  S2      = S1 + NN * S1S;       // t2 [n][b8][f4], stride 36
    float*  s_small = S2 + NN * S2S;
    int*    s_rp    = (int*)(s_small + SMALLSZ);

    const int tid  = threadIdx.x;
    const int wid  = tid >> 5;
    const int lane = tid & 31;
    const int b0   = blockIdx.x * BT;

    // ---- stage rp + small weights ----
    for (int i = tid; i <= NN; i += THREADS) s_rp[i] = g_row_ptr[i];
    for (int i = tid; i < 96;  i += THREADS) s_small[O_W1 + i] = W1[i];
    for (int i = tid; i < 8;   i += THREADS) s_small[O_B1 + i] = b1[i];
    for (int i = tid; i < 32;  i += THREADS) s_small[O_W2 + i] = W2[i];
    for (int i = tid; i < 4;   i += THREADS) s_small[O_B2 + i] = b2[i];
    for (int i = tid; i < 8;   i += THREADS) s_small[O_W3 + i] = W3[i];
    for (int i = tid; i < 2;   i += THREADS) s_small[O_B3 + i] = b3[i];
    for (int i = tid; i < 120; i += THREADS) s_small[O_BF1 + i] = bf1[i];
    for (int i = tid; i < 84;  i += THREADS) s_small[O_BF2 + i] = bf2[i];
    for (int i = tid; i < 10;  i += THREADS) s_small[O_BF3 + i] = bf3[i];
    __syncthreads();

    // ========== T1: t1 = x @ W1 -> S1[n][b][f]  (packed f32x2) =======
    for (int idx = tid; idx < NN * BT; idx += THREADS) {
        const int b = idx / NN, n = idx - b * NN;
        const int g = b0 + b;
        float xa[12];
        if (g < B) {
            const float4* xp = (const float4*)(x + ((size_t)g * NN + n) * 12);
            float4 v0 = xp[0], v1 = xp[1], v2 = xp[2];
            xa[0] = v0.x; xa[1] = v0.y; xa[2]  = v0.z; xa[3]  = v0.w;
            xa[4] = v1.x; xa[5] = v1.y; xa[6]  = v1.z; xa[7]  = v1.w;
            xa[8] = v2.x; xa[9] = v2.y; xa[10] = v2.z; xa[11] = v2.w;
        } else {
            #pragma unroll
            for (int c = 0; c < 12; c++) xa[c] = 0.0f;
        }
        ull p0 = 0, p1 = 0, p2 = 0, p3 = 0;
        #pragma unroll
        for (int c = 0; c < 12; c++) {
            const ull xb = bcast2(xa[c]);
            const ull* wrow = (const ull*)(s_small + O_W1 + c * 8);
            p0 = ffma2(xb, wrow[0], p0);
            p1 = ffma2(xb, wrow[1], p1);
            p2 = ffma2(xb, wrow[2], p2);
            p3 = ffma2(xb, wrow[3], p3);
        }
        float* dst = S1 + n * S1S + b * 8;
        *(ulonglong2*)dst       = make_ulonglong2(p0, p1);
        *(ulonglong2*)(dst + 4) = make_ulonglong2(p2, p3);
    }
    __syncthreads();

    // ========== A1: h1 = tanh(agg(t1)+b1); t2 = h1@W2 -> S2 ==========
    // half-warp per edge, 2 edges per lane per iter, SW-pipelined edge
    // prefetch; lh owns float4: b = lh>>1, fq = (lh&1)*4
    {
        const int h  = lane >> 4;
        const int lh = lane & 15;
        const int fq = (lh & 1) * 4;
        float w2r[4][4];
        #pragma unroll
        for (int i = 0; i < 4; i++)
            #pragma unroll
            for (int f2 = 0; f2 < 4; f2++)
                w2r[i][f2] = s_small[O_W2 + (fq + i) * 4 + f2];
        const float4 b1v = *(const float4*)(s_small + O_B1 + fq);
        const float* S1p = S1 + lh * 4;

        for (int n = wid; n < NN; n += NWARP) {
            const int j0 = s_rp[n], j1 = s_rp[n + 1];
            ull a01 = 0, a23 = 0;
            float2 e0 = __ldg(&g_csr_e[j0 + h]);
            float2 e1 = __ldg(&g_csr_e[j0 + 2 + h]);
            int j = j0;
            #pragma unroll 1
            for (; j + 4 < j1; j += 4) {
                const float2 f0 = __ldg(&g_csr_e[j + 4 + h]);
                const float2 f1 = __ldg(&g_csr_e[j + 6 + h]);
                const ulonglong2 v0 =
                    *(const ulonglong2*)(S1p + __float_as_int(e0.y) * S1S);
                const ulonglong2 v1 =
                    *(const ulonglong2*)(S1p + __float_as_int(e1.y) * S1S);
                const ull w0 = bcast2(e0.x);
                const ull w1 = bcast2(e1.x);
                a01 = ffma2(v0.x, w0, a01);
                a23 = ffma2(v0.y, w0, a23);
                a01 = ffma2(v1.x, w1, a01);
                a23 = ffma2(v1.y, w1, a23);
                e0 = f0; e1 = f1;
            }
            {   // tail (last 4 edges)
                const ulonglong2 v0 =
                    *(const ulonglong2*)(S1p + __float_as_int(e0.y) * S1S);
                const ulonglong2 v1 =
                    *(const ulonglong2*)(S1p + __float_as_int(e1.y) * S1S);
                const ull w0 = bcast2(e0.x);
                const ull w1 = bcast2(e1.x);
                a01 = ffma2(v0.x, w0, a01);
                a23 = ffma2(v0.y, w0, a23);
                a01 = ffma2(v1.x, w1, a01);
                a23 = ffma2(v1.y, w1, a23);
            }
            const float2 u0 = unpack2(a01), u1 = unpack2(a23);
            float ax = u0.x, ay = u0.y, az = u1.x, aw = u1.y;
            ax += __shfl_xor_sync(~0u, ax, 16);
            ay += __shfl_xor_sync(~0u, ay, 16);
            az += __shfl_xor_sync(~0u, az, 16);
            aw += __shfl_xor_sync(~0u, aw, 16);
            const float tx = htanh(ax + b1v.x);
            const float ty = htanh(ay + b1v.y);
            const float tz = htanh(az + b1v.z);
            const float tw = htanh(aw + b1v.w);
            float4 p;
            p.x = tx * w2r[0][0] + ty * w2r[1][0] + tz * w2r[2][0] + tw * w2r[3][0];
            p.y = tx * w2r[0][1] + ty * w2r[1][1] + tz * w2r[2][1] + tw * w2r[3][1];
            p.z = tx * w2r[0][2] + ty * w2r[1][2] + tz * w2r[2][2] + tw * w2r[3][2];
            p.w = tx * w2r[0][3] + ty * w2r[1][3] + tz * w2r[2][3] + tw * w2r[3][3];
            p.x += __shfl_xor_sync(~0u, p.x, 1);
            p.y += __shfl_xor_sync(~0u, p.y, 1);
            p.z += __shfl_xor_sync(~0u, p.z, 1);
            p.w += __shfl_xor_sync(~0u, p.w, 1);
            if (lane < 16 && !(lane & 1))
                *(float4*)(S2 + n * S2S + (lh >> 1) * 4) = p;
        }
    }
    __syncthreads();

    // ========== A2: h2 = tanh(agg(t2)+b2); t3 = h2@W3 -> S1 (t3) =====
    // quarter-warp per edge; lb owns float4, SW-pipelined edge prefetch
    {
        const int q  = lane >> 3;
        const int lb = lane & 7;
        const float4 b2v = *(const float4*)(s_small + O_B2);
        float w30[4], w31[4];
        #pragma unroll
        for (int f = 0; f < 4; f++) {
            w30[f] = s_small[O_W3 + f * 2 + 0];
            w31[f] = s_small[O_W3 + f * 2 + 1];
        }
        const float* S2p = S2 + lb * 4;
        for (int n = wid; n < NN; n += NWARP) {
            const int j0 = s_rp[n], j1 = s_rp[n + 1];
            ull a01 = 0, a23 = 0;
            float2 e = __ldg(&g_csr_e[j0 + q]);
            int j = j0;
            #pragma unroll 1
            for (; j + 4 < j1; j += 4) {
                const float2 f = __ldg(&g_csr_e[j + 4 + q]);
                const ulonglong2 v =
                    *(const ulonglong2*)(S2p + __float_as_int(e.y) * S2S);
                const ull ww = bcast2(e.x);
                a01 = ffma2(v.x, ww, a01);
                a23 = ffma2(v.y, ww, a23);
                e = f;
            }
            {   // tail
                const ulonglong2 v =
                    *(const ulonglong2*)(S2p + __float_as_int(e.y) * S2S);
                const ull ww = bcast2(e.x);
                a01 = ffma2(v.x, ww, a01);
                a23 = ffma2(v.y, ww, a23);
            }
            const float2 u0 = unpack2(a01), u1 = unpack2(a23);
            float ax = u0.x, ay = u0.y, az = u1.x, aw = u1.y;
            #pragma unroll
            for (int off = 8; off <= 16; off <<= 1) {
                ax += __shfl_xor_sync(~0u, ax, off);
                ay += __shfl_xor_sync(~0u, ay, off);
                az += __shfl_xor_sync(~0u, az, off);
                aw += __shfl_xor_sync(~0u, aw, off);
            }
            const float t0 = htanh(ax + b2v.x);
            const float t1 = htanh(ay + b2v.y);
            const float t2 = htanh(az + b2v.z);
            const float t3 = htanh(aw + b2v.w);
            const float p0 = t0 * w30[0] + t1 * w30[1] + t2 * w30[2] + t3 * w30[3];
            const float p1 = t0 * w31[0] + t1 * w31[1] + t2 * w31[2] + t3 * w31[3];
            if (lane < 8)
                *(float2*)(S1 + n * T3S + lb * 2) = make_float2(p0, p1);
        }
    }
    __syncthreads();

    // ========== A3: h3 = agg(t3)+b3 -> xfc[b][2n+c] in S2 ============
    {
        const int o  = lane >> 3;
        const int lb = lane & 7;
        const float b3x = s_small[O_B3 + 0];
        const float b3y = s_small[O_B3 + 1];
        const float* T3p = S1 + lb * 2;
        for (int n = wid; n < NN; n += NWARP) {
            const int j0 = s_rp[n], j1 = s_rp[n + 1];
            float ax = 0.0f, ay = 0.0f;
            float2 e = __ldg(&g_csr_e[j0 + o]);
            int j = j0;
            #pragma unroll 1
            for (; j + 4 < j1; j += 4) {
                const float2 f = __ldg(&g_csr_e[j + 4 + o]);
                const float2 v = *(const float2*)(T3p + __float_as_int(e.y) * T3S);
                ax += e.x * v.x;
                ay += e.x * v.y;
                e = f;
            }
            {   // tail
                const float2 v = *(const float2*)(T3p + __float_as_int(e.y) * T3S);
                ax += e.x * v.x;
                ay += e.x * v.y;
            }
            #pragma unroll
            for (int off = 8; off <= 16; off <<= 1) {
                ax += __shfl_xor_sync(~0u, ax, off);
                ay += __shfl_xor_sync(~0u, ay, off);
            }
            if (lane < 8)
                *(float2*)(S2 + lb * XFS + 2 * n) = make_float2(ax + b3x, ay + b3y);
        }
        // zero xfc pad k = 462, 463 (read by the padded FC1 loop)
        if (tid < 16)
            S2[(tid >> 1) * XFS + 462 + (tid & 1)] = 0.0f;
    }
    __syncthreads();

    // ========== FC1: xfc[8,464] @ Wf1[462,120] + bf1 -> elu -> S1 ====
    // 480 active threads: kh (4 k-quarters of 116) x jg (60: 2 j) x bq (2: 4 b)
    {
        const int kh = tid >> 7;            // 0..3
        const int r  = tid & 127;           // 0..127
        const int jg = r >> 1;              // 0..63 (active < 60)
        const int bq = r & 1;
        const bool active = jg < 60;
        float acc[2][4];
        #pragma unroll
        for (int j = 0; j < 2; j++)
            #pragma unroll
            for (int i = 0; i < 4; i++) acc[j][i] = 0.0f;

        if (active) {
            const int j0 = jg * 2;
            const float* wb = Wf1 + j0;
            const float* x0 = S2 + (bq * 4 + 0) * XFS;
            const float* x1 = S2 + (bq * 4 + 1) * XFS;
            const float* x2 = S2 + (bq * 4 + 2) * XFS;
            const float* x3 = S2 + (bq * 4 + 3) * XFS;
            const int k0 = kh * 116;
            #pragma unroll 1
            for (int k = k0; k < k0 + 116; k += 4) {
                const float4 a0 = *(const float4*)(x0 + k);
                const float4 a1 = *(const float4*)(x1 + k);
                const float4 a2 = *(const float4*)(x2 + k);
                const float4 a3 = *(const float4*)(x3 + k);
                const float2 w0 = __ldg((const float2*)(wb + (k + 0) * 120));
                const float2 w1 = __ldg((const float2*)(wb + (k + 1) * 120));
                const float2 w2 = __ldg((const float2*)(wb + (k + 2) * 120));
                const float2 w3 = __ldg((const float2*)(wb + (k + 3) * 120));
                acc[0][0] += a0.x * w0.x + a0.y * w1.x + a0.z * w2.x + a0.w * w3.x;
                acc[1][0] += a0.x * w0.y + a0.y * w1.y + a0.z * w2.y + a0.w * w3.y;
                acc[0][1] += a1.x * w0.x + a1.y * w1.x + a1.z * w2.x + a1.w * w3.x;
                acc[1][1] += a1.x * w0.y + a1.y * w1.y + a1.z * w2.y + a1.w * w3.y;
                acc[0][2] += a2.x * w0.x + a2.y * w1.x + a2.z * w2.x + a2.w * w3.x;
                acc[1][2] += a2.x * w0.y + a2.y * w1.y + a2.z * w2.y + a2.w * w3.y;
                acc[0][3] += a3.x * w0.x + a3.y * w1.x + a3.z * w2.x + a3.w * w3.x;
                acc[1][3] += a3.x * w0.y + a3.y * w1.y + a3.z * w2.y + a3.w * w3.y;
            }
            if (kh > 0) {
                // write partials to dead S1 scratch (beyond h1 region)
                float* scr = S1 + 4096 + ((kh - 1) * 120 + r) * 8;
                *(float4*)scr = make_float4(acc[0][0], acc[1][0], acc[0][1], acc[1][1]);
                *(float4*)(scr + 4) = make_float4(acc[0][2], acc[1][2], acc[0][3], acc[1][3]);
            }
        }
        __syncthreads();
        if (active && kh == 0) {
            const int j0 = jg * 2;
            const float bfa = s_small[O_BF1 + j0];
            const float bfb = s_small[O_BF1 + j0 + 1];
            #pragma unroll
            for (int p = 0; p < 3; p++) {
                const float* scr = S1 + 4096 + (p * 120 + r) * 8;
                const float4 s0 = *(const float4*)scr;
                const float4 s1 = *(const float4*)(scr + 4);
                acc[0][0] += s0.x; acc[1][0] += s0.y;
                acc[0][1] += s0.z; acc[1][1] += s0.w;
                acc[0][2] += s1.x; acc[1][2] += s1.y;
                acc[0][3] += s1.z; acc[1][3] += s1.w;
            }
            const int bb = bq * 4;
            S1[(bb + 0) * H1S + j0]     = elu1(acc[0][0] + bfa);
            S1[(bb + 0) * H1S + j0 + 1] = elu1(acc[1][0] + bfb);
            S1[(bb + 1) * H1S + j0]     = elu1(acc[0][1] + bfa);
            S1[(bb + 1) * H1S + j0 + 1] = elu1(acc[1][1] + bfb);
            S1[(bb + 2) * H1S + j0]     = elu1(acc[0][2] + bfa);
            S1[(bb + 2) * H1S + j0 + 1] = elu1(acc[1][2] + bfb);
            S1[(bb + 3) * H1S + j0]     = elu1(acc[0][3] + bfa);
            S1[(bb + 3) * H1S + j0 + 1] = elu1(acc[1][3] + bfb);
        }
    }
    __syncthreads();

    // ========== FC2: h1[8,120] @ Wf2[120,84] + bf2 -> elu -> S2 ======
    if (tid < 336) {
        const int b = tid & 7, jg = tid >> 3;   // jg 0..41
        const int j0 = jg * 2;
        float2 acc = make_float2(s_small[O_BF2 + j0], s_small[O_BF2 + j0 + 1]);
        const float* xin = S1 + b * H1S;
        const float* wb  = Wf2 + j0;
        #pragma unroll 2
        for (int k = 0; k < 120; k += 4) {
            const float4 v  = *(const float4*)(xin + k);
            const float2 w0 = __ldg((const float2*)(wb + (k + 0) * 84));
            const float2 w1 = __ldg((const float2*)(wb + (k + 1) * 84));
            const float2 w2 = __ldg((const float2*)(wb + (k + 2) * 84));
            const float2 w3 = __ldg((const float2*)(wb + (k + 3) * 84));
            acc.x += v.x * w0.x + v.y * w1.x + v.z * w2.x + v.w * w3.x;
            acc.y += v.x * w0.y + v.y * w1.y + v.z * w2.y + v.w * w3.y;
        }
        S2[b * H2S + j0 + 0] = elu1(acc.x);
        S2[b * H2S + j0 + 1] = elu1(acc.y);
    }
    __syncthreads();

    // ========== FC3: h2[8,84] @ Wf3[84,10] + bf3 -> out ==============
    if (tid < 80) {
        const int b = tid & 7, j = tid >> 3;    // j 0..9
        float acc = s_small[O_BF3 + j];
        const float* xin = S2 + b * H2S;
        #pragma unroll 3
        for (int k = 0; k < 84; k += 4) {
            const float4 v = *(const float4*)(xin + k);
            acc += v.x * __ldg(Wf3 + (k + 0) * 10 + j);
            acc += v.y * __ldg(Wf3 + (k + 1) * 10 + j);
            acc += v.z * __ldg(Wf3 + (k + 2) * 10 + j);
            acc += v.w * __ldg(Wf3 + (k + 3) * 10 + j);
        }
        const int g = b0 + b;
        if (g < B) out[(size_t)g * 10 + j] = acc;
    }
}

// =====================================================================
extern "C" void kernel_launch(void* const* d_in, const int* in_sizes, int n_in,
                              void* d_out, int out_size) {
    const float* x   = (const float*)d_in[0];
    const void*  ei  = d_in[1];
    const float* W1  = (const float*)d_in[2];
    const float* b1  = (const float*)d_in[3];
    const float* W2  = (const float*)d_in[4];
    const float* b2  = (const float*)d_in[5];
    const float* W3  = (const float*)d_in[6];
    const float* b3  = (const float*)d_in[7];
    const float* Wf1 = (const float*)d_in[8];
    const float* bf1 = (const float*)d_in[9];
    const float* Wf2 = (const float*)d_in[10];
    const float* bf2 = (const float*)d_in[11];
    const float* Wf3 = (const float*)d_in[12];
    const float* bf3 = (const float*)d_in[13];
    float* out = (float*)d_out;

    const int B = in_sizes[0] / (NN * 12);
    const int E = in_sizes[1] / 2;

    prep_kernel<<<1, 256>>>(ei, E);

    static int smem_set = 0;
    if (!smem_set) {
        cudaFuncSetAttribute(gcn_fused_kernel,
                             cudaFuncAttributeMaxDynamicSharedMemorySize,
                             SM_BYTES);
        smem_set = 1;
    }

    const int blocks = (B + BT - 1) / BT;
    gcn_fused_kernel<<<blocks, THREADS, SM_BYTES>>>(
        x, W1, b1, W2, b2, W3, b3, Wf1, bf1, Wf2, bf2, Wf3, bf3,
        out, B);
}